// round 16
// baseline (speedup 1.0000x reference)
#include <cuda_runtime.h>
#include <cuda_fp16.h>
#include <math.h>
#include <stdint.h>

// Problem constants (fixed by the dataset)
#define NN      8000
#define MPAD    8064        // 63 * 128
#define ERAW    64000
#define ETOT    (ERAW + NN)
#define FIN     3201
#define K2MAX   3264        // FIN padded to multiple of 64
#define HMAX    1024
#define BN_CHUNKS 20
#define BN_ROWS   (NN / BN_CHUNKS)
#define BSLOT   ((long)HMAX * K2MAX)

// ---------------- scratch (static device globals; no allocation) -------------
__device__ __half g_h    [(long)NN * HMAX];
__device__ __half g_xl   [(long)MPAD * HMAX];
__device__ __half g_xr   [(long)MPAD * HMAX];
__device__ __half g_Ah   [(long)MPAD * K2MAX];
__device__ __half g_BtAll[8 * BSLOT];       // per-layer transposed fp16 weights
__device__ int    g_cnt  [NN + 32];
__device__ int    g_cur  [NN];
__device__ int    g_off  [NN + 1];
__device__ int    g_csrc [ETOT];
__device__ float  g_bnp1 [BN_CHUNKS * K2MAX];
__device__ float  g_bnp2 [BN_CHUNKS * K2MAX];
__device__ float  g_mean [FIN];
__device__ float  g_rstd [FIN];

struct WPtrs { const float* p[8]; };

// ------------------------------ PTX helpers ----------------------------------
__device__ __forceinline__ uint32_t smem_u32(const void* p) {
    uint32_t a;
    asm("{ .reg .u64 t; cvta.to.shared.u64 t, %1; cvt.u32.u64 %0, t; }"
        : "=r"(a) : "l"(p));
    return a;
}
__device__ __forceinline__ void cp_async16(uint32_t dst, const void* src) {
    asm volatile("cp.async.ca.shared.global [%0], [%1], 16;"
                 :: "r"(dst), "l"(src) : "memory");
}
__device__ __forceinline__ void cp_commit() {
    asm volatile("cp.async.commit_group;" ::: "memory");
}
template<int NG> __device__ __forceinline__ void cp_wait() {
    asm volatile("cp.async.wait_group %0;" :: "n"(NG) : "memory");
}
__device__ __forceinline__ void mma16816(float* c, const uint32_t* a,
                                         uint32_t b0, uint32_t b1) {
    asm volatile(
        "mma.sync.aligned.m16n8k16.row.col.f32.f16.f16.f32 "
        "{%0,%1,%2,%3}, {%4,%5,%6,%7}, {%8,%9}, {%0,%1,%2,%3};"
        : "+f"(c[0]), "+f"(c[1]), "+f"(c[2]), "+f"(c[3])
        : "r"(a[0]), "r"(a[1]), "r"(a[2]), "r"(a[3]), "r"(b0), "r"(b1));
}
__device__ __forceinline__ void ldm_x4(uint32_t* r, uint32_t addr) {
    asm volatile("ldmatrix.sync.aligned.m8n8.x4.shared.b16 {%0,%1,%2,%3}, [%4];"
                 : "=r"(r[0]), "=r"(r[1]), "=r"(r[2]), "=r"(r[3]) : "r"(addr));
}

// ------------------------------- small utils --------------------------------
__global__ void fill2_int_kernel(int* a, int na, int* b, int nb) {
    int i = blockIdx.x * blockDim.x + threadIdx.x;
    if (i < na) a[i] = 0;
    if (i < nb) b[i] = 0;
}

__global__ void count_edges_kernel(const int* __restrict__ ei, int E) {
    int i = blockIdx.x * blockDim.x + threadIdx.x;
    if (i >= E + NN) return;
    int d = (i < E) ? ei[E + i] : (i - E);
    atomicAdd(&g_cnt[d], 1);
}

// single-block exclusive scan over g_cnt -> g_off (shfl + vectorized loads)
__global__ void scan_kernel() {
    __shared__ int wsum[8];
    int tid = threadIdx.x;
    int lane = tid & 31, wid = tid >> 5;
    const int CH = 32;
    int base = tid * CH;
    int vals[CH];
    #pragma unroll
    for (int i = 0; i < CH / 4; i++) {
        int4 v = *(const int4*)&g_cnt[base + i * 4];
        vals[i * 4 + 0] = v.x; vals[i * 4 + 1] = v.y;
        vals[i * 4 + 2] = v.z; vals[i * 4 + 3] = v.w;
    }
    int s = 0;
    #pragma unroll
    for (int i = 0; i < CH; i++) s += vals[i];
    int own = s;
    #pragma unroll
    for (int o = 1; o < 32; o <<= 1) {
        int v = __shfl_up_sync(0xffffffffu, s, o);
        if (lane >= o) s += v;
    }
    if (lane == 31) wsum[wid] = s;
    __syncthreads();
    if (wid == 0 && lane < 8) {
        int w = wsum[lane];
        #pragma unroll
        for (int o = 1; o < 8; o <<= 1) {
            int v = __shfl_up_sync(0xffu, w, o);
            if (lane >= o) w += v;
        }
        wsum[lane] = w - wsum[lane];
    }
    __syncthreads();
    int acc = wsum[wid] + s - own;
    #pragma unroll
    for (int i = 0; i < CH; i++) {
        int n = base + i;
        if (n < NN) { g_off[n] = acc; acc += vals[i]; }
    }
    if (tid == 255) g_off[NN] = acc;
}

__global__ void scatter_kernel(const int* __restrict__ ei, int E) {
    int i = blockIdx.x * blockDim.x + threadIdx.x;
    if (i >= E + NN) return;
    int s, d;
    if (i < E) { s = ei[i]; d = ei[E + i]; }
    else       { s = d = i - E; }
    int pos = g_off[d] + atomicAdd(&g_cur[d], 1);
    g_csrc[pos] = s;
}

// ------------- all 8 weight transposes, packed 1D grid (no dead blocks) ------
#define TCUM0 0
#define TCUM1 3264
#define TCUM2 6528
#define TCUM3 7040
#define TCUM4 7552
#define TCUM5 7808
#define TCUM6 8064
#define TCUM7 8320
#define TCUM8 8576

__global__ void transpose_all_kernel(WPtrs wp) {
    const int cum[9]  = { TCUM0, TCUM1, TCUM2, TCUM3, TCUM4, TCUM5, TCUM6, TCUM7, TCUM8 };
    const int KinA[4] = { FIN, 1024, 512, 512 };
    const int K2A[4]  = { K2MAX, 1024, 512, 512 };
    const int NcA[4]  = { 1024, 512, 512, 512 };
    int b = blockIdx.x;
    int z = 0;
    #pragma unroll
    for (int i = 1; i < 8; i++) if (b >= cum[i]) z = i;
    int t = b - cum[z];
    int L = z >> 1;
    int Kin = KinA[L], K2 = K2A[L], Nc = NcA[L];
    int ktiles = K2 >> 5;
    int kx = t % ktiles, ny = t / ktiles;
    int k0 = kx * 32, n0 = ny * 32;
    const float* W = wp.p[z];
    __half* dst = g_BtAll + (long)z * BSLOT;

    int tx = threadIdx.x, ty = threadIdx.y;
    __shared__ float tile[32][33];
    #pragma unroll
    for (int j = 0; j < 4; j++) {
        int k = k0 + ty + 8 * j;
        float v = 0.0f;
        if (k < Kin) v = W[(long)k * Nc + n0 + tx];
        tile[ty + 8 * j][tx] = v;
    }
    __syncthreads();
    #pragma unroll
    for (int j = 0; j < 4; j++) {
        int n = n0 + ty + 8 * j;
        dst[(long)n * K2 + k0 + tx] = __float2half(tile[tx][ty + 8 * j]);
    }
}

// ------------------------------- batchnorm ----------------------------------
// src may be fp32 (layer 0 input x) or fp16 (hidden h)
__global__ void bn_partial_kernel(const void* __restrict__ hsrc, int F, int ishalf) {
    int f = blockIdx.x * blockDim.x + threadIdx.x;
    if (f >= F) return;
    int r0 = blockIdx.y * BN_ROWS;
    float s = 0.0f, s2 = 0.0f;
    if (ishalf) {
        const __half* p = (const __half*)hsrc;
        for (int r = r0; r < r0 + BN_ROWS; r++) {
            float v = __half2float(p[(long)r * F + f]);
            s += v; s2 += v * v;
        }
    } else {
        const float* p = (const float*)hsrc;
        for (int r = r0; r < r0 + BN_ROWS; r++) {
            float v = p[(long)r * F + f];
            s += v; s2 += v * v;
        }
    }
    g_bnp1[blockIdx.y * F + f] = s;
    g_bnp2[blockIdx.y * F + f] = s2;
}

__global__ void bn_final_kernel(int F) {
    int f = blockIdx.x * blockDim.x + threadIdx.x;
    if (f >= F) return;
    float s = 0.0f, s2 = 0.0f;
    #pragma unroll
    for (int c = 0; c < BN_CHUNKS; c++) { s += g_bnp1[c * F + f]; s2 += g_bnp2[c * F + f]; }
    float m = s / (float)NN;
    float var = s2 / (float)NN - m * m;
    g_mean[f] = m;
    g_rstd[f] = rsqrtf(var + 1e-5f);
}

// BN-apply + optional relu + fp16 quantize + padding; grid=(cdiv(K2,256), MPAD)
__global__ void bn_apply_half_kernel(const void* __restrict__ in, int Fin, int K2,
                                     const float* __restrict__ gam, const float* __restrict__ bet,
                                     int relu, int ishalf, __half* __restrict__ A) {
    int col = blockIdx.x * blockDim.x + threadIdx.x;
    int row = blockIdx.y;
    if (col >= K2) return;
    float v = 0.0f;
    if (row < NN && col < Fin) {
        float raw = ishalf ? __half2float(((const __half*)in)[(long)row * Fin + col])
                           : ((const float*)in)[(long)row * Fin + col];
        v = (raw - g_mean[col]) * g_rstd[col] * gam[col] + bet[col];
        if (relu) v = fmaxf(v, 0.0f);
    }
    A[(long)row * K2 + col] = __float2half(v);
}

// ------ mma.sync fp16 GEMM: both xl/xr in ONE block (A loaded once) ----------
#define STR       40
#define STR2      (STR * 2)
#define BUF_B     (128 * STR2)
#define A_OFF     0
#define B0_OFF    (2 * BUF_B)
#define B1_OFF    (4 * BUF_B)
#define GSMEM     (6 * BUF_B)               // 61440 bytes

__global__ __launch_bounds__(256, 1) void gemm_fp16_dual2(
    const __half* __restrict__ Ah,
    const __half* __restrict__ Bt0, const __half* __restrict__ Bt1,
    __half* __restrict__ C0, __half* __restrict__ C1, int N, int K2)
{
    extern __shared__ char sm[];
    uint32_t sb = smem_u32(sm);
    const int tid = threadIdx.x;
    const int wid = tid >> 5, lane = tid & 31;
    const int wm = wid & 1, wn = wid >> 1;
    const int g = lane >> 2, q = lane & 3;
    const long row0 = (long)blockIdx.y * 128;
    const long col0 = (long)blockIdx.x * 128;

    float acc0[4][4][4], acc1[4][4][4];
    #pragma unroll
    for (int i = 0; i < 4; i++)
        #pragma unroll
        for (int j = 0; j < 4; j++)
            #pragma unroll
            for (int t = 0; t < 4; t++) { acc0[i][j][t] = 0.0f; acc1[i][j][t] = 0.0f; }

    const int NS = K2 >> 5;

    auto issue = [&](int s, int buf) {
        int k0 = s << 5;
        #pragma unroll
        for (int it = 0; it < 2; it++) {
            int c = tid + (it << 8);
            int row = c >> 2;
            int kc = (c & 3) * 8;
            uint32_t so = (uint32_t)(buf * BUF_B + row * STR2 + kc * 2);
            long ga = (row0 + row) * K2 + k0 + kc;
            long gb = (col0 + row) * K2 + k0 + kc;
            cp_async16(sb + A_OFF + so, Ah + ga);
            cp_async16(sb + B0_OFF + so, Bt0 + gb);
            cp_async16(sb + B1_OFF + so, Bt1 + gb);
        }
        cp_commit();
    };

    const uint32_t aoff = (uint32_t)((wm * 64 + (lane & 15)) * STR2 + (lane >> 4) * 16);
    const uint32_t boff = (uint32_t)((wn * 32 + ((lane >> 4) & 1) * 8 + (lane & 7)) * STR2
                                     + ((lane >> 3) & 1) * 16);

    issue(0, 0);

    for (int s = 0; s < NS; s++) {
        int buf = s & 1;
        if (s + 1 < NS) { issue(s + 1, buf ^ 1); cp_wait<1>(); }
        else            { cp_wait<0>(); }
        __syncthreads();

        uint32_t a_b  = sb + A_OFF + buf * BUF_B;
        uint32_t b0_b = sb + B0_OFF + buf * BUF_B;
        uint32_t b1_b = sb + B1_OFF + buf * BUF_B;

        #pragma unroll
        for (int kk = 0; kk < 2; kk++) {
            uint32_t kByte = (uint32_t)(kk * 32);
            uint32_t Bf0[8], Bf1[8];
            #pragma unroll
            for (int jp = 0; jp < 2; jp++) {
                uint32_t off = boff + kByte + (uint32_t)(jp * 16 * STR2);
                ldm_x4(&Bf0[jp * 4], b0_b + off);
                ldm_x4(&Bf1[jp * 4], b1_b + off);
            }
            #pragma unroll
            for (int i = 0; i < 4; i++) {
                uint32_t off = aoff + kByte + (uint32_t)(i * 16 * STR2);
                uint32_t af[4];
                ldm_x4(af, a_b + off);
                #pragma unroll
                for (int j = 0; j < 4; j++) mma16816(acc0[i][j], af, Bf0[2*j], Bf0[2*j+1]);
                #pragma unroll
                for (int j = 0; j < 4; j++) mma16816(acc1[i][j], af, Bf1[2*j], Bf1[2*j+1]);
            }
        }
        __syncthreads();
    }

    #pragma unroll
    for (int i = 0; i < 4; i++) {
        long r = row0 + wm * 64 + i * 16 + g;
        #pragma unroll
        for (int j = 0; j < 4; j++) {
            long cc = col0 + wn * 32 + j * 8 + 2 * q;
            *(__half2*)(C0 + r * N + cc)       = __floats2half2_rn(acc0[i][j][0], acc0[i][j][1]);
            *(__half2*)(C0 + (r + 8) * N + cc) = __floats2half2_rn(acc0[i][j][2], acc0[i][j][3]);
            *(__half2*)(C1 + r * N + cc)       = __floats2half2_rn(acc1[i][j][0], acc1[i][j][1]);
            *(__half2*)(C1 + (r + 8) * N + cc) = __floats2half2_rn(acc1[i][j][2], acc1[i][j][3]);
        }
    }
}

// -------- fused attention: warp per (node, head), online softmax -------------
__device__ __forceinline__ void unpack16(const uint4& a, const uint4& b, float* v) {
    const __half2* pa = (const __half2*)&a;
    const __half2* pb = (const __half2*)&b;
    #pragma unroll
    for (int t = 0; t < 4; t++) {
        float2 f = __half22float2(pa[t]);
        v[2 * t] = f.x; v[2 * t + 1] = f.y;
    }
    #pragma unroll
    for (int t = 0; t < 4; t++) {
        float2 f = __half22float2(pb[t]);
        v[8 + 2 * t] = f.x; v[8 + 2 * t + 1] = f.y;
    }
}

__global__ __launch_bounds__(256) void attn_warp_kernel(
    const __half* __restrict__ xl, const __half* __restrict__ xr,
    const float* __restrict__ att, const float* __restrict__ bias,
    __half* __restrict__ out, int H, int relu)
{
    const int gw = (blockIdx.x * blockDim.x + threadIdx.x) >> 5;
    const int lane = threadIdx.x & 31;
    if (gw >= NN * H) return;
    const int n = gw / H, h = gw % H;
    const int C = 512;
    const int HC = H * C;
    const int f0 = h * C + lane * 16;

    float attv[16], xrv[16];
    #pragma unroll
    for (int j = 0; j < 16; j += 4) {
        float4 w = *(const float4*)(att + f0 + j);
        attv[j] = w.x; attv[j + 1] = w.y; attv[j + 2] = w.z; attv[j + 3] = w.w;
    }
    {
        uint4 xa = *(const uint4*)(xr + (long)n * HC + f0);
        uint4 xb = *(const uint4*)(xr + (long)n * HC + f0 + 8);
        unpack16(xa, xb, xrv);
    }

    const int st = g_off[n], en = g_off[n + 1];

    float m = -3.0e38f, ssum = 0.0f;
    float acc[16];
    #pragma unroll
    for (int j = 0; j < 16; j++) acc[j] = 0.0f;

    long base0 = (long)g_csrc[st] * HC + f0;
    uint4 ra = *(const uint4*)(xl + base0);
    uint4 rb = *(const uint4*)(xl + base0 + 8);

    for (int p = st; p < en; p++) {
        uint4 ca = ra, cb = rb;
        if (p + 1 < en) {
            long b = (long)g_csrc[p + 1] * HC + f0;
            ra = *(const uint4*)(xl + b);
            rb = *(const uint4*)(xl + b + 8);
        }
        float av[16];
        unpack16(ca, cb, av);

        float part = 0.0f;
        #pragma unroll
        for (int j = 0; j < 16; j++) {
            float z = av[j] + xrv[j];
            z = (z > 0.f) ? z : 0.2f * z;
            part = fmaf(z, attv[j], part);
        }
        #pragma unroll
        for (int o = 16; o; o >>= 1) part += __shfl_xor_sync(0xffffffffu, part, o);

        float mnew = fmaxf(m, part);
        float corr = __expf(m - mnew);
        float w = __expf(part - mnew);
        ssum = ssum * corr + w;
        #pragma unroll
        for (int j = 0; j < 16; j++) acc[j] = fmaf(acc[j], corr, w * av[j]);
        m = mnew;
    }

    float inv = 1.0f / (ssum * (float)(en - st));
    __half2 o2[8];
    #pragma unroll
    for (int j = 0; j < 16; j += 4) {
        float4 b = *(const float4*)(bias + f0 + j);
        float v0 = acc[j]     * inv + b.x;
        float v1 = acc[j + 1] * inv + b.y;
        float v2 = acc[j + 2] * inv + b.z;
        float v3 = acc[j + 3] * inv + b.w;
        if (relu) {
            v0 = fmaxf(v0, 0.f); v1 = fmaxf(v1, 0.f);
            v2 = fmaxf(v2, 0.f); v3 = fmaxf(v3, 0.f);
        }
        o2[j / 2]     = __floats2half2_rn(v0, v1);
        o2[j / 2 + 1] = __floats2half2_rn(v2, v3);
    }
    *(uint4*)(out + (long)n * HC + f0)     = *(uint4*)&o2[0];
    *(uint4*)(out + (long)n * HC + f0 + 8) = *(uint4*)&o2[4];
}

// -------------------- fused head + gather: warp per train idx ----------------
__global__ void head_gather_kernel(const __half* __restrict__ h, const float* __restrict__ Wh,
                                   const float* __restrict__ bh,
                                   const float* __restrict__ y, const int* __restrict__ tidx,
                                   float* __restrict__ out, int nt) {
    int warp = (blockIdx.x * blockDim.x + threadIdx.x) >> 5;
    int lane = threadIdx.x & 31;
    if (warp >= nt) return;
    int n = tidx[warp];
    const __half* p = h + (long)n * 512;
    int c = lane * 16;
    uint4 ha = *(const uint4*)(p + c);
    uint4 hb = *(const uint4*)(p + c + 8);
    float hv[16];
    unpack16(ha, hb, hv);
    float s = 0.0f;
    #pragma unroll
    for (int j = 0; j < 16; j += 4) {
        float4 w = *(const float4*)(Wh + c + j);
        s += hv[j] * w.x + hv[j + 1] * w.y + hv[j + 2] * w.z + hv[j + 3] * w.w;
    }
    #pragma unroll
    for (int o = 16; o; o >>= 1) s += __shfl_xor_sync(0xffffffffu, s, o);
    if (lane == 0) {
        out[warp]      = 1.0f / (1.0f + expf(-(s + bh[0])));
        out[nt + warp] = y[n];
    }
}

// --------------------------------- host side ---------------------------------
static inline long cdiv(long a, long b) { return (a + b - 1) / b; }

extern "C" void kernel_launch(void* const* d_in, const int* in_sizes, int n_in,
                              void* d_out, int out_size) {
    const float* x    = (const float*)d_in[0];
    const int*   ei   = (const int*)  d_in[1];
    const float* y    = (const float*)d_in[2];
    const int*   tidx = (const int*)  d_in[3];
    const float* bn0g = (const float*)d_in[4];
    const float* bn0b = (const float*)d_in[5];
    const float* Wl[4] = { (const float*)d_in[6],  (const float*)d_in[12],
                           (const float*)d_in[18], (const float*)d_in[24] };
    const float* Wr[4] = { (const float*)d_in[7],  (const float*)d_in[13],
                           (const float*)d_in[19], (const float*)d_in[25] };
    const float* att[4] = { (const float*)d_in[8],  (const float*)d_in[14],
                            (const float*)d_in[20], (const float*)d_in[26] };
    const float* bia[4] = { (const float*)d_in[9],  (const float*)d_in[15],
                            (const float*)d_in[21], (const float*)d_in[27] };
    const float* bng[3] = { (const float*)d_in[10], (const float*)d_in[16],
                            (const float*)d_in[22] };
    const float* bnb[3] = { (const float*)d_in[11], (const float*)d_in[17],
                            (const float*)d_in[23] };
    const float* Wh = (const float*)d_in[28];
    const float* bh = (const float*)d_in[29];
    float* out = (float*)d_out;

    int E  = in_sizes[1] / 2;
    int nt = in_sizes[3];

    int *cnt, *cur;
    __half *h, *xl, *xr, *ah, *btall;
    cudaGetSymbolAddress((void**)&h,     g_h);
    cudaGetSymbolAddress((void**)&xl,    g_xl);
    cudaGetSymbolAddress((void**)&xr,    g_xr);
    cudaGetSymbolAddress((void**)&cnt,   g_cnt);
    cudaGetSymbolAddress((void**)&cur,   g_cur);
    cudaGetSymbolAddress((void**)&ah,    g_Ah);
    cudaGetSymbolAddress((void**)&btall, g_BtAll);

    cudaFuncSetAttribute(gemm_fp16_dual2, cudaFuncAttributeMaxDynamicSharedMemorySize, GSMEM);

    const int T = 256;
    int Etot = E + NN;

    // CSR build
    fill2_int_kernel<<<cdiv(NN + 32, T), T>>>(cnt, NN + 32, cur, NN);
    count_edges_kernel<<<cdiv(Etot, T), T>>>(ei, E);
    // all 8 weight transposes, one packed-grid kernel (independent of CSR)
    {
        WPtrs wp;
        for (int L = 0; L < 4; L++) { wp.p[2 * L] = Wl[L]; wp.p[2 * L + 1] = Wr[L]; }
        dim3 blk(32, 8);
        transpose_all_kernel<<<TCUM8, blk>>>(wp);
    }
    scan_kernel<<<1, 256>>>();
    scatter_kernel<<<cdiv(Etot, T), T>>>(ei, E);

    int Kin [4] = { FIN, 1024, 512, 512 };
    int K2s [4] = { K2MAX, 1024, 512, 512 };
    int Ncs [4] = { 1024, 512, 512, 512 };
    int heads[4] = { 2, 1, 1, 1 };

    for (int L = 0; L < 4; L++) {
        int KI = Kin[L], K2 = K2s[L], Nc = Ncs[L];
        int H = heads[L];
        __half* btl = btall + (long)(2 * L) * BSLOT;
        __half* btr = btall + (long)(2 * L + 1) * BSLOT;

        // BN stats + apply/quantize/pad
        {
            const void* src = (L == 0) ? (const void*)x : (const void*)h;
            const float* g = (L == 0) ? bn0g : bng[L - 1];
            const float* b = (L == 0) ? bn0b : bnb[L - 1];
            int relu = (L == 0) ? 0 : 1;
            int ishalf = (L == 0) ? 0 : 1;
            dim3 grid(cdiv(KI, T), BN_CHUNKS);
            bn_partial_kernel<<<grid, T>>>(src, KI, ishalf);
            bn_final_kernel<<<cdiv(KI, T), T>>>(KI);
            dim3 agrid(cdiv(K2, T), MPAD);
            bn_apply_half_kernel<<<agrid, T>>>(src, KI, K2, g, b, relu, ishalf, ah);
        }

        // fused GEMM pair (shared A): xl = A @ Wl, xr = A @ Wr
        {
            dim3 grid(Nc / 128, MPAD / 128);
            gemm_fp16_dual2<<<grid, 256, GSMEM>>>(ah, btl, btr, xl, xr, Nc, K2);
        }

        // fused attention: warp per (node, head)
        {
            int relu_here = (L == 3) ? 1 : 0;
            int warps = NN * H;
            attn_warp_kernel<<<cdiv((long)warps * 32, T), T>>>(xl, xr, att[L], bia[L],
                                                               h, H, relu_here);
        }
    }

    head_gather_kernel<<<cdiv((long)nt * 32, T), T>>>(h, Wh, bh, y, tidx, out, nt);
}

// round 17
// speedup vs baseline: 1.0371x; 1.0371x over previous
#include <cuda_runtime.h>
#include <cuda_fp16.h>
#include <math.h>
#include <stdint.h>

// Problem constants (fixed by the dataset)
#define NN      8000
#define MPAD    8064        // 63 * 128
#define ERAW    64000
#define ETOT    (ERAW + NN)
#define FIN     3201
#define K2MAX   3264        // FIN padded to multiple of 64
#define HMAX    1024
#define BN_CHUNKS 20
#define BN_ROWS   (NN / BN_CHUNKS)
#define BSLOT   ((long)HMAX * K2MAX)

// ---------------- scratch (static device globals; no allocation) -------------
__device__ __half g_h    [(long)NN * HMAX];
__device__ __half g_xl   [(long)MPAD * HMAX];
__device__ __half g_xr   [(long)MPAD * HMAX];
__device__ __half g_Ah   [(long)MPAD * K2MAX];
__device__ __half g_BtAll[8 * BSLOT];       // per-layer transposed fp16 weights
__device__ int    g_cnt  [NN + 32];
__device__ int    g_cur  [NN];
__device__ int    g_off  [NN + 1];
__device__ int    g_csrc [ETOT];
__device__ float  g_bnp1 [BN_CHUNKS * K2MAX];
__device__ float  g_bnp2 [BN_CHUNKS * K2MAX];
__device__ float  g_mean [FIN];
__device__ float  g_rstd [FIN];

struct WPtrs { const float* p[8]; };

// ------------------------------ PTX helpers ----------------------------------
__device__ __forceinline__ uint32_t smem_u32(const void* p) {
    uint32_t a;
    asm("{ .reg .u64 t; cvta.to.shared.u64 t, %1; cvt.u32.u64 %0, t; }"
        : "=r"(a) : "l"(p));
    return a;
}
__device__ __forceinline__ void cp_async16(uint32_t dst, const void* src) {
    asm volatile("cp.async.ca.shared.global [%0], [%1], 16;"
                 :: "r"(dst), "l"(src) : "memory");
}
__device__ __forceinline__ void cp_commit() {
    asm volatile("cp.async.commit_group;" ::: "memory");
}
template<int NG> __device__ __forceinline__ void cp_wait() {
    asm volatile("cp.async.wait_group %0;" :: "n"(NG) : "memory");
}
__device__ __forceinline__ void mma16816(float* c, const uint32_t* a,
                                         uint32_t b0, uint32_t b1) {
    asm volatile(
        "mma.sync.aligned.m16n8k16.row.col.f32.f16.f16.f32 "
        "{%0,%1,%2,%3}, {%4,%5,%6,%7}, {%8,%9}, {%0,%1,%2,%3};"
        : "+f"(c[0]), "+f"(c[1]), "+f"(c[2]), "+f"(c[3])
        : "r"(a[0]), "r"(a[1]), "r"(a[2]), "r"(a[3]), "r"(b0), "r"(b1));
}
__device__ __forceinline__ void ldm_x4(uint32_t* r, uint32_t addr) {
    asm volatile("ldmatrix.sync.aligned.m8n8.x4.shared.b16 {%0,%1,%2,%3}, [%4];"
                 : "=r"(r[0]), "=r"(r[1]), "=r"(r[2]), "=r"(r[3]) : "r"(addr));
}

// ------------------------------- small utils --------------------------------
__global__ void fill2_int_kernel(int* a, int na, int* b, int nb) {
    int i = blockIdx.x * blockDim.x + threadIdx.x;
    if (i < na) a[i] = 0;
    if (i < nb) b[i] = 0;
}

__global__ void count_edges_kernel(const int* __restrict__ ei, int E) {
    int i = blockIdx.x * blockDim.x + threadIdx.x;
    if (i >= E + NN) return;
    int d = (i < E) ? ei[E + i] : (i - E);
    atomicAdd(&g_cnt[d], 1);
}

// single-block exclusive scan over g_cnt -> g_off (shfl + vectorized loads)
__global__ void scan_kernel() {
    __shared__ int wsum[8];
    int tid = threadIdx.x;
    int lane = tid & 31, wid = tid >> 5;
    const int CH = 32;
    int base = tid * CH;
    int vals[CH];
    #pragma unroll
    for (int i = 0; i < CH / 4; i++) {
        int4 v = *(const int4*)&g_cnt[base + i * 4];
        vals[i * 4 + 0] = v.x; vals[i * 4 + 1] = v.y;
        vals[i * 4 + 2] = v.z; vals[i * 4 + 3] = v.w;
    }
    int s = 0;
    #pragma unroll
    for (int i = 0; i < CH; i++) s += vals[i];
    int own = s;
    #pragma unroll
    for (int o = 1; o < 32; o <<= 1) {
        int v = __shfl_up_sync(0xffffffffu, s, o);
        if (lane >= o) s += v;
    }
    if (lane == 31) wsum[wid] = s;
    __syncthreads();
    if (wid == 0 && lane < 8) {
        int w = wsum[lane];
        #pragma unroll
        for (int o = 1; o < 8; o <<= 1) {
            int v = __shfl_up_sync(0xffu, w, o);
            if (lane >= o) w += v;
        }
        wsum[lane] = w - wsum[lane];
    }
    __syncthreads();
    int acc = wsum[wid] + s - own;
    #pragma unroll
    for (int i = 0; i < CH; i++) {
        int n = base + i;
        if (n < NN) { g_off[n] = acc; acc += vals[i]; }
    }
    if (tid == 255) g_off[NN] = acc;
}

__global__ void scatter_kernel(const int* __restrict__ ei, int E) {
    int i = blockIdx.x * blockDim.x + threadIdx.x;
    if (i >= E + NN) return;
    int s, d;
    if (i < E) { s = ei[i]; d = ei[E + i]; }
    else       { s = d = i - E; }
    int pos = g_off[d] + atomicAdd(&g_cur[d], 1);
    g_csrc[pos] = s;
}

// ------------- all 8 weight transposes, packed 1D grid (no dead blocks) ------
#define TCUM0 0
#define TCUM1 3264
#define TCUM2 6528
#define TCUM3 7040
#define TCUM4 7552
#define TCUM5 7808
#define TCUM6 8064
#define TCUM7 8320
#define TCUM8 8576

__global__ void transpose_all_kernel(WPtrs wp) {
    const int cum[9]  = { TCUM0, TCUM1, TCUM2, TCUM3, TCUM4, TCUM5, TCUM6, TCUM7, TCUM8 };
    const int KinA[4] = { FIN, 1024, 512, 512 };
    const int K2A[4]  = { K2MAX, 1024, 512, 512 };
    const int NcA[4]  = { 1024, 512, 512, 512 };
    int b = blockIdx.x;
    int z = 0;
    #pragma unroll
    for (int i = 1; i < 8; i++) if (b >= cum[i]) z = i;
    int t = b - cum[z];
    int L = z >> 1;
    int Kin = KinA[L], K2 = K2A[L], Nc = NcA[L];
    int ktiles = K2 >> 5;
    int kx = t % ktiles, ny = t / ktiles;
    int k0 = kx * 32, n0 = ny * 32;
    const float* W = wp.p[z];
    __half* dst = g_BtAll + (long)z * BSLOT;

    int tx = threadIdx.x, ty = threadIdx.y;
    __shared__ float tile[32][33];
    #pragma unroll
    for (int j = 0; j < 4; j++) {
        int k = k0 + ty + 8 * j;
        float v = 0.0f;
        if (k < Kin) v = W[(long)k * Nc + n0 + tx];
        tile[ty + 8 * j][tx] = v;
    }
    __syncthreads();
    #pragma unroll
    for (int j = 0; j < 4; j++) {
        int n = n0 + ty + 8 * j;
        dst[(long)n * K2 + k0 + tx] = __float2half(tile[tx][ty + 8 * j]);
    }
}

// ------------------------------- batchnorm ----------------------------------
// src may be fp32 (layer 0 input x) or fp16 (hidden h)
__global__ void bn_partial_kernel(const void* __restrict__ hsrc, int F, int ishalf) {
    int f = blockIdx.x * blockDim.x + threadIdx.x;
    if (f >= F) return;
    int r0 = blockIdx.y * BN_ROWS;
    float s = 0.0f, s2 = 0.0f;
    if (ishalf) {
        const __half* p = (const __half*)hsrc;
        for (int r = r0; r < r0 + BN_ROWS; r++) {
            float v = __half2float(p[(long)r * F + f]);
            s += v; s2 += v * v;
        }
    } else {
        const float* p = (const float*)hsrc;
        for (int r = r0; r < r0 + BN_ROWS; r++) {
            float v = p[(long)r * F + f];
            s += v; s2 += v * v;
        }
    }
    g_bnp1[blockIdx.y * F + f] = s;
    g_bnp2[blockIdx.y * F + f] = s2;
}

__global__ void bn_final_kernel(int F) {
    int f = blockIdx.x * blockDim.x + threadIdx.x;
    if (f >= F) return;
    float s = 0.0f, s2 = 0.0f;
    #pragma unroll
    for (int c = 0; c < BN_CHUNKS; c++) { s += g_bnp1[c * F + f]; s2 += g_bnp2[c * F + f]; }
    float m = s / (float)NN;
    float var = s2 / (float)NN - m * m;
    g_mean[f] = m;
    g_rstd[f] = rsqrtf(var + 1e-5f);
}

// BN-apply + optional relu + fp16 quantize + padding; grid=(cdiv(K2,256), MPAD)
__global__ void bn_apply_half_kernel(const void* __restrict__ in, int Fin, int K2,
                                     const float* __restrict__ gam, const float* __restrict__ bet,
                                     int relu, int ishalf, __half* __restrict__ A) {
    int col = blockIdx.x * blockDim.x + threadIdx.x;
    int row = blockIdx.y;
    if (col >= K2) return;
    float v = 0.0f;
    if (row < NN && col < Fin) {
        float raw = ishalf ? __half2float(((const __half*)in)[(long)row * Fin + col])
                           : ((const float*)in)[(long)row * Fin + col];
        v = (raw - g_mean[col]) * g_rstd[col] * gam[col] + bet[col];
        if (relu) v = fmaxf(v, 0.0f);
    }
    A[(long)row * K2 + col] = __float2half(v);
}

// ------------------ mma.sync fp16 GEMM, fused xl/xr (z-dim) ------------------
#define STR       40
#define STR2      (STR * 2)
#define BUF_B     (128 * STR2)
#define A_OFF     0
#define B_OFF     (2 * BUF_B)
#define GSMEM     (4 * BUF_B)               // 40960 bytes

__global__ __launch_bounds__(256) void gemm_fp16_dual(
    const __half* __restrict__ Ah,
    const __half* __restrict__ Bt0, const __half* __restrict__ Bt1,
    __half* __restrict__ C0, __half* __restrict__ C1, int N, int K2)
{
    extern __shared__ char sm[];
    uint32_t sb = smem_u32(sm);
    const int tid = threadIdx.x;
    const int wid = tid >> 5, lane = tid & 31;
    const int wm = wid & 1, wn = wid >> 1;
    const int g = lane >> 2, q = lane & 3;
    const long row0 = (long)blockIdx.y * 128;
    const long col0 = (long)blockIdx.x * 128;
    const __half* Bt = blockIdx.z ? Bt1 : Bt0;
    __half* C = blockIdx.z ? C1 : C0;

    float acc[4][4][4];
    #pragma unroll
    for (int i = 0; i < 4; i++)
        #pragma unroll
        for (int j = 0; j < 4; j++)
            #pragma unroll
            for (int t = 0; t < 4; t++) acc[i][j][t] = 0.0f;

    const int NS = K2 >> 5;

    auto issue = [&](int s, int buf) {
        int k0 = s << 5;
        #pragma unroll
        for (int it = 0; it < 2; it++) {
            int c = tid + (it << 8);
            int row = c >> 2;
            int kc = (c & 3) * 8;
            uint32_t so = (uint32_t)(buf * BUF_B + row * STR2 + kc * 2);
            long ga = (row0 + row) * K2 + k0 + kc;
            long gb = (col0 + row) * K2 + k0 + kc;
            cp_async16(sb + A_OFF + so, Ah + ga);
            cp_async16(sb + B_OFF + so, Bt + gb);
        }
        cp_commit();
    };

    const uint32_t aoff = (uint32_t)((wm * 64 + (lane & 15)) * STR2 + (lane >> 4) * 16);
    const uint32_t boff = (uint32_t)((wn * 32 + ((lane >> 4) & 1) * 8 + (lane & 7)) * STR2
                                     + ((lane >> 3) & 1) * 16);

    issue(0, 0);

    for (int s = 0; s < NS; s++) {
        int buf = s & 1;
        if (s + 1 < NS) { issue(s + 1, buf ^ 1); cp_wait<1>(); }
        else            { cp_wait<0>(); }
        __syncthreads();

        uint32_t a_b = sb + A_OFF + buf * BUF_B;
        uint32_t b_b = sb + B_OFF + buf * BUF_B;

        #pragma unroll
        for (int kk = 0; kk < 2; kk++) {
            uint32_t kByte = (uint32_t)(kk * 32);
            uint32_t Bf[8];
            #pragma unroll
            for (int jp = 0; jp < 2; jp++) {
                uint32_t off = boff + kByte + (uint32_t)(jp * 16 * STR2);
                ldm_x4(&Bf[jp * 4], b_b + off);
            }
            #pragma unroll
            for (int i = 0; i < 4; i++) {
                uint32_t off = aoff + kByte + (uint32_t)(i * 16 * STR2);
                uint32_t af[4];
                ldm_x4(af, a_b + off);
                #pragma unroll
                for (int j = 0; j < 4; j++) mma16816(acc[i][j], af, Bf[2*j], Bf[2*j+1]);
            }
        }
        __syncthreads();
    }

    #pragma unroll
    for (int i = 0; i < 4; i++) {
        long r = row0 + wm * 64 + i * 16 + g;
        #pragma unroll
        for (int j = 0; j < 4; j++) {
            long cc = col0 + wn * 32 + j * 8 + 2 * q;
            *(__half2*)(C + r * N + cc)       = __floats2half2_rn(acc[i][j][0], acc[i][j][1]);
            *(__half2*)(C + (r + 8) * N + cc) = __floats2half2_rn(acc[i][j][2], acc[i][j][3]);
        }
    }
}

// -------- fused attention: warp per (node, head), online softmax -------------
__device__ __forceinline__ void unpack16(const uint4& a, const uint4& b, float* v) {
    const __half2* pa = (const __half2*)&a;
    const __half2* pb = (const __half2*)&b;
    #pragma unroll
    for (int t = 0; t < 4; t++) {
        float2 f = __half22float2(pa[t]);
        v[2 * t] = f.x; v[2 * t + 1] = f.y;
    }
    #pragma unroll
    for (int t = 0; t < 4; t++) {
        float2 f = __half22float2(pb[t]);
        v[8 + 2 * t] = f.x; v[8 + 2 * t + 1] = f.y;
    }
}

__global__ __launch_bounds__(256) void attn_warp_kernel(
    const __half* __restrict__ xl, const __half* __restrict__ xr,
    const float* __restrict__ att, const float* __restrict__ bias,
    __half* __restrict__ out, int H, int relu)
{
    const int gw = (blockIdx.x * blockDim.x + threadIdx.x) >> 5;
    const int lane = threadIdx.x & 31;
    if (gw >= NN * H) return;
    const int n = gw / H, h = gw % H;
    const int C = 512;
    const int HC = H * C;
    const int f0 = h * C + lane * 16;

    float attv[16], xrv[16];
    #pragma unroll
    for (int j = 0; j < 16; j += 4) {
        float4 w = *(const float4*)(att + f0 + j);
        attv[j] = w.x; attv[j + 1] = w.y; attv[j + 2] = w.z; attv[j + 3] = w.w;
    }
    {
        uint4 xa = *(const uint4*)(xr + (long)n * HC + f0);
        uint4 xb = *(const uint4*)(xr + (long)n * HC + f0 + 8);
        unpack16(xa, xb, xrv);
    }

    const int st = g_off[n], en = g_off[n + 1];

    float m = -3.0e38f, ssum = 0.0f;
    float acc[16];
    #pragma unroll
    for (int j = 0; j < 16; j++) acc[j] = 0.0f;

    long base0 = (long)g_csrc[st] * HC + f0;
    uint4 ra = *(const uint4*)(xl + base0);
    uint4 rb = *(const uint4*)(xl + base0 + 8);

    for (int p = st; p < en; p++) {
        uint4 ca = ra, cb = rb;
        if (p + 1 < en) {
            long b = (long)g_csrc[p + 1] * HC + f0;
            ra = *(const uint4*)(xl + b);
            rb = *(const uint4*)(xl + b + 8);
        }
        float av[16];
        unpack16(ca, cb, av);

        float part = 0.0f;
        #pragma unroll
        for (int j = 0; j < 16; j++) {
            float z = av[j] + xrv[j];
            z = (z > 0.f) ? z : 0.2f * z;
            part = fmaf(z, attv[j], part);
        }
        #pragma unroll
        for (int o = 16; o; o >>= 1) part += __shfl_xor_sync(0xffffffffu, part, o);

        float mnew = fmaxf(m, part);
        float corr = __expf(m - mnew);
        float w = __expf(part - mnew);
        ssum = ssum * corr + w;
        #pragma unroll
        for (int j = 0; j < 16; j++) acc[j] = fmaf(acc[j], corr, w * av[j]);
        m = mnew;
    }

    float inv = 1.0f / (ssum * (float)(en - st));
    __half2 o2[8];
    #pragma unroll
    for (int j = 0; j < 16; j += 4) {
        float4 b = *(const float4*)(bias + f0 + j);
        float v0 = acc[j]     * inv + b.x;
        float v1 = acc[j + 1] * inv + b.y;
        float v2 = acc[j + 2] * inv + b.z;
        float v3 = acc[j + 3] * inv + b.w;
        if (relu) {
            v0 = fmaxf(v0, 0.f); v1 = fmaxf(v1, 0.f);
            v2 = fmaxf(v2, 0.f); v3 = fmaxf(v3, 0.f);
        }
        o2[j / 2]     = __floats2half2_rn(v0, v1);
        o2[j / 2 + 1] = __floats2half2_rn(v2, v3);
    }
    *(uint4*)(out + (long)n * HC + f0)     = *(uint4*)&o2[0];
    *(uint4*)(out + (long)n * HC + f0 + 8) = *(uint4*)&o2[4];
}

// -------------------- fused head + gather: warp per train idx ----------------
__global__ void head_gather_kernel(const __half* __restrict__ h, const float* __restrict__ Wh,
                                   const float* __restrict__ bh,
                                   const float* __restrict__ y, const int* __restrict__ tidx,
                                   float* __restrict__ out, int nt) {
    int warp = (blockIdx.x * blockDim.x + threadIdx.x) >> 5;
    int lane = threadIdx.x & 31;
    if (warp >= nt) return;
    int n = tidx[warp];
    const __half* p = h + (long)n * 512;
    int c = lane * 16;
    uint4 ha = *(const uint4*)(p + c);
    uint4 hb = *(const uint4*)(p + c + 8);
    float hv[16];
    unpack16(ha, hb, hv);
    float s = 0.0f;
    #pragma unroll
    for (int j = 0; j < 16; j += 4) {
        float4 w = *(const float4*)(Wh + c + j);
        s += hv[j] * w.x + hv[j + 1] * w.y + hv[j + 2] * w.z + hv[j + 3] * w.w;
    }
    #pragma unroll
    for (int o = 16; o; o >>= 1) s += __shfl_xor_sync(0xffffffffu, s, o);
    if (lane == 0) {
        out[warp]      = 1.0f / (1.0f + expf(-(s + bh[0])));
        out[nt + warp] = y[n];
    }
}

// --------------------------------- host side ---------------------------------
static inline long cdiv(long a, long b) { return (a + b - 1) / b; }

extern "C" void kernel_launch(void* const* d_in, const int* in_sizes, int n_in,
                              void* d_out, int out_size) {
    const float* x    = (const float*)d_in[0];
    const int*   ei   = (const int*)  d_in[1];
    const float* y    = (const float*)d_in[2];
    const int*   tidx = (const int*)  d_in[3];
    const float* bn0g = (const float*)d_in[4];
    const float* bn0b = (const float*)d_in[5];
    const float* Wl[4] = { (const float*)d_in[6],  (const float*)d_in[12],
                           (const float*)d_in[18], (const float*)d_in[24] };
    const float* Wr[4] = { (const float*)d_in[7],  (const float*)d_in[13],
                           (const float*)d_in[19], (const float*)d_in[25] };
    const float* att[4] = { (const float*)d_in[8],  (const float*)d_in[14],
                            (const float*)d_in[20], (const float*)d_in[26] };
    const float* bia[4] = { (const float*)d_in[9],  (const float*)d_in[15],
                            (const float*)d_in[21], (const float*)d_in[27] };
    const float* bng[3] = { (const float*)d_in[10], (const float*)d_in[16],
                            (const float*)d_in[22] };
    const float* bnb[3] = { (const float*)d_in[11], (const float*)d_in[17],
                            (const float*)d_in[23] };
    const float* Wh = (const float*)d_in[28];
    const float* bh = (const float*)d_in[29];
    float* out = (float*)d_out;

    int E  = in_sizes[1] / 2;
    int nt = in_sizes[3];

    int *cnt, *cur;
    __half *h, *xl, *xr, *ah, *btall;
    cudaGetSymbolAddress((void**)&h,     g_h);
    cudaGetSymbolAddress((void**)&xl,    g_xl);
    cudaGetSymbolAddress((void**)&xr,    g_xr);
    cudaGetSymbolAddress((void**)&cnt,   g_cnt);
    cudaGetSymbolAddress((void**)&cur,   g_cur);
    cudaGetSymbolAddress((void**)&ah,    g_Ah);
    cudaGetSymbolAddress((void**)&btall, g_BtAll);

    cudaFuncSetAttribute(gemm_fp16_dual, cudaFuncAttributeMaxDynamicSharedMemorySize, GSMEM);

    const int T = 256;
    int Etot = E + NN;

    // CSR build
    fill2_int_kernel<<<cdiv(NN + 32, T), T>>>(cnt, NN + 32, cur, NN);
    count_edges_kernel<<<cdiv(Etot, T), T>>>(ei, E);
    // all 8 weight transposes, one packed-grid kernel (independent of CSR)
    {
        WPtrs wp;
        for (int L = 0; L < 4; L++) { wp.p[2 * L] = Wl[L]; wp.p[2 * L + 1] = Wr[L]; }
        dim3 blk(32, 8);
        transpose_all_kernel<<<TCUM8, blk>>>(wp);
    }
    scan_kernel<<<1, 256>>>();
    scatter_kernel<<<cdiv(Etot, T), T>>>(ei, E);

    int Kin [4] = { FIN, 1024, 512, 512 };
    int K2s [4] = { K2MAX, 1024, 512, 512 };
    int Ncs [4] = { 1024, 512, 512, 512 };
    int heads[4] = { 2, 1, 1, 1 };

    for (int L = 0; L < 4; L++) {
        int KI = Kin[L], K2 = K2s[L], Nc = Ncs[L];
        int H = heads[L];
        __half* btl = btall + (long)(2 * L) * BSLOT;
        __half* btr = btall + (long)(2 * L + 1) * BSLOT;

        // BN stats + apply/quantize/pad
        {
            const void* src = (L == 0) ? (const void*)x : (const void*)h;
            const float* g = (L == 0) ? bn0g : bng[L - 1];
            const float* b = (L == 0) ? bn0b : bnb[L - 1];
            int relu = (L == 0) ? 0 : 1;
            int ishalf = (L == 0) ? 0 : 1;
            dim3 grid(cdiv(KI, T), BN_CHUNKS);
            bn_partial_kernel<<<grid, T>>>(src, KI, ishalf);
            bn_final_kernel<<<cdiv(KI, T), T>>>(KI);
            dim3 agrid(cdiv(K2, T), MPAD);
            bn_apply_half_kernel<<<agrid, T>>>(src, KI, K2, g, b, relu, ishalf, ah);
        }

        // fused GEMM pair (z-dim split): xl = A @ Wl, xr = A @ Wr
        {
            dim3 grid(Nc / 128, MPAD / 128, 2);
            gemm_fp16_dual<<<grid, 256, GSMEM>>>(ah, btl, btr, xl, xr, Nc, K2);
        }

        // fused attention: warp per (node, head)
        {
            int relu_here = (L == 3) ? 1 : 0;
            int warps = NN * H;
            attn_warp_kernel<<<cdiv((long)warps * 32, T), T>>>(xl, xr, att[L], bia[L],
                                                               h, H, relu_here);
        }
    }

    head_gather_kernel<<<cdiv((long)nt * 32, T), T>>>(h, Wh, bh, y, tidx, out, nt);
}